// round 6
// baseline (speedup 1.0000x reference)
#include <cuda_runtime.h>
#include <math.h>

// Shapes fixed by the reference:
//  B=16,T=32 -> BT=512 ; NP=8, NG=4, J=14, H=256
#define BT      512
#define NPERM   1680                 // P(8,4)
#define HEAT_N  (512 * 256 * 256)    // 33,554,432 floats
#define N4      (HEAT_N / 4)         // 8,388,608 float4
#define NBLK    1036                 // 148 SMs * 7 blocks = one wave
#define NMB     16                   // dedicated match blocks
#define NHB     (NBLK - NMB)         // 1020 heat-streaming blocks

#define INV_HEAT (1.0f / (float)HEAT_N)
#define INV_BT   (1.0f / 512.0f)
#define INV_POSE (1.0f / (512.0f * 8.0f * 14.0f))

__device__ float        g_part[NBLK];   // per-block heat partial
__device__ float        g_match[BT];    // per-(b,t) combined match contribution
__device__ unsigned int g_count;        // completion counter (self-resetting)

// Monotone float->uint map: equal floats -> equal keys, order preserved.
__device__ __forceinline__ unsigned f2ord(float v) {
    unsigned u = __float_as_uint(v);
    return (u & 0x80000000u) ? ~u : (u | 0x80000000u);
}

__device__ __forceinline__ unsigned long long umin64(unsigned long long a,
                                                     unsigned long long b) {
    return a < b ? a : b;
}

// Lexicographic rank -> k-permutation of range(8), k=4 (itertools order).
// Used only twice per cell (final decode), so cost is irrelevant here.
__device__ __forceinline__ void decode_perm(int r, int* p) {
    const int divs[4] = {210, 30, 5, 1};
    unsigned mask = 0xFFu;
#pragma unroll
    for (int k = 0; k < 4; k++) {
        int d = r / divs[k];
        r -= d * divs[k];
        unsigned m = mask;
#pragma unroll
        for (int q = 0; q < 7; q++)
            if (q < d) m &= (m - 1);
        int idx = __ffs(m) - 1;
        mask &= ~(1u << idx);
        p[k] = idx;
    }
}

__global__ void __launch_bounds__(256, 7)
k_fused(const float4* __restrict__ ha,   // hor_heatmap as float4
        const float4* __restrict__ hb,   // gt_heatmap  as float4
        const float* __restrict__ po_all,   // hor_offset  (BT,8,2)
        const float* __restrict__ ps_all,   // hor_bsize   (BT,8,4)
        const float* __restrict__ pc_all,   // hor_center  (BT,8,2)
        const float* __restrict__ sc_all,   // scores      (BT,8)
        const float* __restrict__ pp_all,   // x_pose3d    (BT,8,14,3)
        const float* __restrict__ gs_all,   // gt_boxes_wh (BT,4,4)
        const float* __restrict__ go_all,   // gt_offset   (BT,4,2)
        const float* __restrict__ gc_all,   // gt_center   (BT,4,2)
        const float* __restrict__ gp_all,   // gt_pose3d   (BT,4,14,3)
        float* __restrict__ out)
{
    const int bid = blockIdx.x;
    const int t   = threadIdx.x;

    __shared__ float sC[8 * 64];      // per-warp cost matrices: [warp][Cb 32 | Cp 32]
    __shared__ float sred[256];
    __shared__ bool  isLast;

    if (bid < NMB) {
        // --------------------------------------------------------------
        // Dedicated match blocks: one warp per (b,t) cell, 4 cells/warp.
        // Runs concurrently with heat streaming on the other 1020 blocks.
        // --------------------------------------------------------------
        const int warp = t >> 5, lane = t & 31;
        float* sCb = sC + warp * 64;
        float* sCp = sCb + 32;

        for (int c = 0; c < 4; c++) {
            const int bt = (bid * 8 + warp) * 4 + c;   // 16*8*4 = 512 cells

            const float* pp = pp_all + bt * 8 * 42;
            const float* gp = gp_all + bt * 4 * 42;

            // Cost matrices: lane = i*4+j (exactly 32 entries).
            {
                int i = lane >> 2, j = lane & 3;
                float dx = pc_all[bt * 16 + 2 * i]     - gc_all[bt * 8 + 2 * j];
                float dy = pc_all[bt * 16 + 2 * i + 1] - gc_all[bt * 8 + 2 * j + 1];
                sCb[lane] = sqrtf(dx * dx + dy * dy) - sc_all[bt * 8 + i];
                float s = 0.f;
                const float* pi = pp + i * 42;
                const float* gj = gp + j * 42;
#pragma unroll
                for (int k = 0; k < 42; k++) {
                    float d = pi[k] - gj[k];
                    s += d * d;
                }
                sCp[lane] = sqrtf(s);
            }
            __syncwarp();

            // Sweep all 1680 combos via (d0,d1) prefixes: 56 prefixes x 30.
            // rank = ((d0*7+d1)*6+d2)*5+d3 matches itertools lexicographic
            // order; min over (orderedFloat<<32 | rank) = exact first-argmin.
            unsigned long long kb = ~0ull, kp = ~0ull;
            for (int p = lane; p < 56; p += 32) {
                int d0 = p / 7, d1 = p - d0 * 7;
                int i0 = d0;
                int i1 = d1 + (d1 >= d0);
                int a1 = min(i0, i1), b1 = max(i0, i1);
                float sb01 = sCb[i0 * 4 + 0] + sCb[i1 * 4 + 1];
                float sp01 = sCp[i0 * 4 + 0] + sCp[i1 * 4 + 1];
                int rbase = p * 30;
#pragma unroll
                for (int d2 = 0; d2 < 6; d2++) {
                    int i2 = d2;
                    i2 += (i2 >= a1);
                    i2 += (i2 >= b1);
                    float sb2 = sb01 + sCb[i2 * 4 + 2];
                    float sp2 = sp01 + sCp[i2 * 4 + 2];
                    int a2, b2, c2;
                    if (i2 < a1)      { a2 = i2; b2 = a1; c2 = b1; }
                    else if (i2 < b1) { a2 = a1; b2 = i2; c2 = b1; }
                    else              { a2 = a1; b2 = b1; c2 = i2; }
#pragma unroll
                    for (int d3 = 0; d3 < 5; d3++) {
                        int i3 = d3;
                        i3 += (i3 >= a2);
                        i3 += (i3 >= b2);
                        i3 += (i3 >= c2);
                        float tb = sb2 + sCb[i3 * 4 + 3];
                        float tp = sp2 + sCp[i3 * 4 + 3];
                        unsigned r = (unsigned)(rbase + d2 * 5 + d3);
                        kb = umin64(kb, ((unsigned long long)f2ord(tb) << 32) | r);
                        kp = umin64(kp, ((unsigned long long)f2ord(tp) << 32) | r);
                    }
                }
            }
#pragma unroll
            for (int o = 16; o > 0; o >>= 1) {
                kb = umin64(kb, __shfl_xor_sync(0xffffffffu, kb, o));
                kp = umin64(kp, __shfl_xor_sync(0xffffffffu, kp, o));
            }
            int pb[4], pq[4];
            decode_perm((int)(kb & 0xFFFFFFFFu), pb);
            decode_perm((int)(kp & 0xFFFFFFFFu), pq);

            // Tail losses: lanes parallel over terms, fixed-order shuffle sum.
            float pose_acc = 0.f, box_acc = 0.f;
            for (int idx = lane; idx < 168; idx += 32) {
                int j = idx / 42, k = idx - j * 42;
                float d = pp[pq[j] * 42 + k] - gp[idx];
                pose_acc += d * d;
            }
            if (lane < 24) {
                int j = lane / 6, w = lane - j * 6;
                int i = pb[j];
                if (w < 2) {
                    box_acc = 0.5f * fabsf(po_all[bt * 16 + i * 2 + w] -
                                           go_all[bt * 8  + j * 2 + w]);
                } else {
                    int k = w - 2;
                    box_acc = 0.25f * fabsf(ps_all[bt * 32 + i * 4 + k] -
                                            gs_all[bt * 16 + j * 4 + k]);
                }
            }
            float v = pose_acc * INV_POSE + box_acc * INV_BT;
#pragma unroll
            for (int o = 16; o > 0; o >>= 1)
                v += __shfl_down_sync(0xffffffffu, v, o);
            if (lane == 0) g_match[bt] = v;
            __syncwarp();
        }
        if (t == 0) g_part[bid] = 0.f;
    } else {
        // --------------------------------------------------------------
        // Heat blocks: pure streaming MSE, R1's proven grid-stride shape,
        // full-width from cycle 0.
        // --------------------------------------------------------------
        float acc = 0.f;
        for (int i = (bid - NMB) * 256 + t; i < N4; i += NHB * 256) {
            float4 x = ha[i];
            float4 y = hb[i];
            float dx = x.x - y.x, dy = x.y - y.y, dz = x.z - y.z, dw = x.w - y.w;
            acc += dx * dx + dy * dy + dz * dz + dw * dw;
        }

        sred[t] = acc;
        __syncthreads();
#pragma unroll
        for (int o = 128; o > 0; o >>= 1) {
            if (t < o) sred[t] += sred[t + o];
            __syncthreads();
        }
        if (t == 0) g_part[bid] = sred[0];
    }

    // ------------------------------------------------------------------
    // Last block to arrive combines (threadFenceReduction pattern).
    // ------------------------------------------------------------------
    if (t == 0) {
        __threadfence();
        unsigned old = atomicAdd(&g_count, 1u);
        isLast = (old == NBLK - 1);
    }
    __syncthreads();

    if (isLast) {
        __threadfence();
        float v = 0.f;
        for (int i = t; i < NBLK; i += 256) v += g_part[i] * INV_HEAT;
        for (int i = t; i < BT;   i += 256) v += g_match[i];
        __syncthreads();            // sred reuse barrier
        sred[t] = v;
        __syncthreads();
#pragma unroll
        for (int o = 128; o > 0; o >>= 1) {
            if (t < o) sred[t] += sred[t + o];
            __syncthreads();
        }
        if (t == 0) {
            out[0]  = sred[0];
            g_count = 0;            // reset for next graph replay
        }
    }
}

extern "C" void kernel_launch(void* const* d_in, const int* in_sizes, int n_in,
                              void* d_out, int out_size) {
    const float* hor_heatmap = (const float*)d_in[0];
    const float* hor_offset  = (const float*)d_in[1];
    const float* hor_bsize   = (const float*)d_in[2];
    const float* hor_center  = (const float*)d_in[3];
    const float* scores      = (const float*)d_in[4];
    const float* x_pose3d    = (const float*)d_in[5];
    const float* gt_heatmap  = (const float*)d_in[6];
    const float* gt_boxes_wh = (const float*)d_in[7];
    const float* gt_offset   = (const float*)d_in[8];
    const float* gt_center   = (const float*)d_in[9];
    const float* gt_pose3d   = (const float*)d_in[10];

    k_fused<<<NBLK, 256>>>((const float4*)hor_heatmap, (const float4*)gt_heatmap,
                           hor_offset, hor_bsize, hor_center, scores, x_pose3d,
                           gt_boxes_wh, gt_offset, gt_center, gt_pose3d,
                           (float*)d_out);
}

// round 7
// speedup vs baseline: 1.3105x; 1.3105x over previous
#include <cuda_runtime.h>
#include <math.h>

// Shapes fixed by the reference:
//  B=16,T=32 -> BT=512 ; NP=8, NG=4, J=14, H=256
#define BT      512
#define HEAT_N  (512 * 256 * 256)    // 33,554,432 floats
#define N4      (HEAT_N / 4)         // 8,388,608 float4
#define NBLK    1024

#define INV_HEAT (1.0f / (float)HEAT_N)
#define INV_BT   (1.0f / 512.0f)
#define INV_POSE (1.0f / (512.0f * 8.0f * 14.0f))

__device__ float        g_part[NBLK];   // per-block heat partial
__device__ float        g_match[BT];    // per-(b,t) combined match contribution
__device__ unsigned int g_count;        // completion counter (self-resetting)

// Monotone float->uint map: equal floats -> equal keys, order preserved.
__device__ __forceinline__ unsigned f2ord(float v) {
    unsigned u = __float_as_uint(v);
    return (u & 0x80000000u) ? ~u : (u | 0x80000000u);
}

__device__ __forceinline__ unsigned long long umin64(unsigned long long a,
                                                     unsigned long long b) {
    return a < b ? a : b;
}

// Lexicographic rank -> k-permutation of range(8), k=4 (itertools order).
// Only used twice per cell for the final decode.
__device__ __forceinline__ void decode_perm(int r, int* p) {
    const int divs[4] = {210, 30, 5, 1};
    unsigned mask = 0xFFu;
#pragma unroll
    for (int k = 0; k < 4; k++) {
        int d = r / divs[k];
        r -= d * divs[k];
        unsigned m = mask;
#pragma unroll
        for (int q = 0; q < 7; q++)
            if (q < d) m &= (m - 1);
        int idx = __ffs(m) - 1;
        mask &= ~(1u << idx);
        p[k] = idx;
    }
}

__global__ void __launch_bounds__(256, 7)
k_fused(const float4* __restrict__ ha,   // hor_heatmap as float4
        const float4* __restrict__ hb,   // gt_heatmap  as float4
        const float* __restrict__ po_all,   // hor_offset  (BT,8,2)
        const float* __restrict__ ps_all,   // hor_bsize   (BT,8,4)
        const float* __restrict__ pc_all,   // hor_center  (BT,8,2)
        const float* __restrict__ sc_all,   // scores      (BT,8)
        const float* __restrict__ pp_all,   // x_pose3d    (BT,8,14,3)
        const float* __restrict__ gs_all,   // gt_boxes_wh (BT,4,4)
        const float* __restrict__ go_all,   // gt_offset   (BT,4,2)
        const float* __restrict__ gc_all,   // gt_center   (BT,4,2)
        const float* __restrict__ gp_all,   // gt_pose3d   (BT,4,14,3)
        float* __restrict__ out)
{
    const int bid = blockIdx.x;
    const int t   = threadIdx.x;

    __shared__ float sred[256];
    __shared__ float sCb[32], sCp[32];
    __shared__ unsigned long long skB[64], skP[64];
    __shared__ int   s_pb[4], s_pq[4];
    __shared__ bool  isLast;

    // ==================================================================
    // Phase 1 (ALL blocks): heatmap MSE — R1's exact measured-6.27TB/s
    // shape: 1024 blocks, power-of-2 grid stride, full width from cycle 0.
    // ==================================================================
    {
        float acc = 0.f;
        for (int i = bid * 256 + t; i < N4; i += NBLK * 256) {
            float4 x = ha[i];
            float4 y = hb[i];
            float dx = x.x - y.x, dy = x.y - y.y, dz = x.z - y.z, dw = x.w - y.w;
            acc += dx * dx + dy * dy + dz * dz + dw * dw;
        }
        sred[t] = acc;
        __syncthreads();
#pragma unroll
        for (int o = 128; o > 0; o >>= 1) {
            if (t < o) sred[t] += sred[t + o];
            __syncthreads();
        }
        if (t == 0) g_part[bid] = sred[0];
    }

    // ==================================================================
    // Phase 2 (blocks 0..511): one match cell per block, all 256 threads.
    // Runs after the stream — DRAM queues drained, loads fast, data then
    // L1-hot for the tail. 512 blocks run concurrently => ~2-3us total.
    // ==================================================================
    if (bid < BT) {
        const int bt = bid;
        const float* pp = pp_all + bt * 8 * 42;
        const float* gp = gp_all + bt * 4 * 42;

        // Cost matrices: entry e = t>>3 (i = e>>2, j = e&3), part q = t&7.
        // Pose: each part sums 6 of the 42 terms (q=7 has none).
        {
            int e = t >> 3, q = t & 7;
            int i = e >> 2, j = e & 3;
            float s = 0.f;
            const float* pi = pp + i * 42;
            const float* gj = gp + j * 42;
            int k0 = q * 6;
#pragma unroll
            for (int c = 0; c < 6; c++) {
                int k = k0 + c;
                if (k < 42) {
                    float d = pi[k] - gj[k];
                    s += d * d;
                }
            }
            sred[t] = s;
            if (q == 0) {
                float dx = pc_all[bt * 16 + 2 * i]     - gc_all[bt * 8 + 2 * j];
                float dy = pc_all[bt * 16 + 2 * i + 1] - gc_all[bt * 8 + 2 * j + 1];
                sCb[e] = sqrtf(dx * dx + dy * dy) - sc_all[bt * 8 + i];
            }
        }
        __syncthreads();
        if (t < 32) {
            float s = 0.f;
#pragma unroll
            for (int q = 0; q < 8; q++) s += sred[t * 8 + q];
            sCp[t] = sqrtf(s);
        }
        __syncthreads();

        // Sweep all 1680 combos: 56 (d0,d1)-prefixes, 30 combos each.
        // rank = ((d0*7+d1)*6+d2)*5+d3 matches itertools lexicographic
        // order; min over (orderedFloat<<32 | rank) = exact first-argmin.
        if (t < 64) { skB[t] = ~0ull; skP[t] = ~0ull; }
        __syncthreads();
        if (t < 56) {
            int d0 = t / 7, d1 = t - d0 * 7;
            int i0 = d0;
            int i1 = d1 + (d1 >= d0);
            int a1 = min(i0, i1), b1 = max(i0, i1);
            float sb01 = sCb[i0 * 4 + 0] + sCb[i1 * 4 + 1];
            float sp01 = sCp[i0 * 4 + 0] + sCp[i1 * 4 + 1];
            unsigned long long kb = ~0ull, kp = ~0ull;
            int rbase = t * 30;
#pragma unroll
            for (int d2 = 0; d2 < 6; d2++) {
                int i2 = d2;
                i2 += (i2 >= a1);
                i2 += (i2 >= b1);
                float sb2 = sb01 + sCb[i2 * 4 + 2];
                float sp2 = sp01 + sCp[i2 * 4 + 2];
                int a2, b2, c2;
                if (i2 < a1)      { a2 = i2; b2 = a1; c2 = b1; }
                else if (i2 < b1) { a2 = a1; b2 = i2; c2 = b1; }
                else              { a2 = a1; b2 = b1; c2 = i2; }
#pragma unroll
                for (int d3 = 0; d3 < 5; d3++) {
                    int i3 = d3;
                    i3 += (i3 >= a2);
                    i3 += (i3 >= b2);
                    i3 += (i3 >= c2);
                    float tb = sb2 + sCb[i3 * 4 + 3];
                    float tp = sp2 + sCp[i3 * 4 + 3];
                    unsigned r = (unsigned)(rbase + d2 * 5 + d3);
                    kb = umin64(kb, ((unsigned long long)f2ord(tb) << 32) | r);
                    kp = umin64(kp, ((unsigned long long)f2ord(tp) << 32) | r);
                }
            }
            skB[t] = kb; skP[t] = kp;
        }
        __syncthreads();
        if (t < 32) {
            unsigned long long kb = umin64(skB[t], skB[t + 32]);
            unsigned long long kp = umin64(skP[t], skP[t + 32]);
#pragma unroll
            for (int o = 16; o > 0; o >>= 1) {
                kb = umin64(kb, __shfl_xor_sync(0xffffffffu, kb, o));
                kp = umin64(kp, __shfl_xor_sync(0xffffffffu, kp, o));
            }
            if (t == 0) {
                int pb[4], pq[4];
                decode_perm((int)(kb & 0xFFFFFFFFu), pb);
                decode_perm((int)(kp & 0xFFFFFFFFu), pq);
#pragma unroll
                for (int j = 0; j < 4; j++) { s_pb[j] = pb[j]; s_pq[j] = pq[j]; }
            }
        }
        __syncthreads();

        // Tail losses: 168 pose terms + 24 box terms, one per thread.
        // Pose data just touched above -> L1-hot.
        {
            float v = 0.f;
            if (t < 168) {
                int j = t / 42, k = t - j * 42;
                float d = pp[s_pq[j] * 42 + k] - gp[t];
                v = d * d * INV_POSE;
            } else if (t < 192) {
                int u = t - 168;
                int j = u / 6, w = u - j * 6;
                int i = s_pb[j];
                if (w < 2) {
                    v = 0.5f * INV_BT * fabsf(po_all[bt * 16 + i * 2 + w] -
                                              go_all[bt * 8  + j * 2 + w]);
                } else {
                    int k = w - 2;
                    v = 0.25f * INV_BT * fabsf(ps_all[bt * 32 + i * 4 + k] -
                                               gs_all[bt * 16 + j * 4 + k]);
                }
            }
            sred[t] = v;
        }
        __syncthreads();
#pragma unroll
        for (int o = 128; o > 0; o >>= 1) {
            if (t < o) sred[t] += sred[t + o];
            __syncthreads();
        }
        if (t == 0) g_match[bt] = sred[0];
    }

    // ==================================================================
    // Phase 3: last block to arrive combines (threadFenceReduction).
    // ==================================================================
    if (t == 0) {
        __threadfence();
        unsigned old = atomicAdd(&g_count, 1u);
        isLast = (old == NBLK - 1);
    }
    __syncthreads();

    if (isLast) {
        __threadfence();
        float v = 0.f;
        for (int i = t; i < NBLK; i += 256) v += g_part[i] * INV_HEAT;
        for (int i = t; i < BT;   i += 256) v += g_match[i];
        __syncthreads();            // sred reuse barrier
        sred[t] = v;
        __syncthreads();
#pragma unroll
        for (int o = 128; o > 0; o >>= 1) {
            if (t < o) sred[t] += sred[t + o];
            __syncthreads();
        }
        if (t == 0) {
            out[0]  = sred[0];
            g_count = 0;            // reset for next graph replay
        }
    }
}

extern "C" void kernel_launch(void* const* d_in, const int* in_sizes, int n_in,
                              void* d_out, int out_size) {
    const float* hor_heatmap = (const float*)d_in[0];
    const float* hor_offset  = (const float*)d_in[1];
    const float* hor_bsize   = (const float*)d_in[2];
    const float* hor_center  = (const float*)d_in[3];
    const float* scores      = (const float*)d_in[4];
    const float* x_pose3d    = (const float*)d_in[5];
    const float* gt_heatmap  = (const float*)d_in[6];
    const float* gt_boxes_wh = (const float*)d_in[7];
    const float* gt_offset   = (const float*)d_in[8];
    const float* gt_center   = (const float*)d_in[9];
    const float* gt_pose3d   = (const float*)d_in[10];

    k_fused<<<NBLK, 256>>>((const float4*)hor_heatmap, (const float4*)gt_heatmap,
                           hor_offset, hor_bsize, hor_center, scores, x_pose3d,
                           gt_boxes_wh, gt_offset, gt_center, gt_pose3d,
                           (float*)d_out);
}